// round 6
// baseline (speedup 1.0000x reference)
#include <cuda_runtime.h>
#include <cuda_bf16.h>

#define BATCH   256
#define NSCORES 50000
#define TOPK    20
#define NBINS   2048
#define RLO     (-7.0f)
#define RHI     (7.0f)
#define THREADS 512

// Bit-trick seed + 2 Newton iterations. Returns approximately -1/d for d > 0.
// (Sign folded so the accumulate can be a single FFMA; negate at the end.)
__device__ __forceinline__ float fast_neg_rcp(float d) {
    float r0 = __uint_as_float(0x7EF311C3u - __float_as_uint(d));
    float t1 = fmaf(d, r0, -2.0f);   // d*r0 - 2
    float m1 = r0 * t1;              // = -r1
    float t2 = fmaf(d, m1, 2.0f);    // 2 - d*r1
    return m1 * t2;                  // = -r2 ~ -1/d  (rel err ~6e-6)
}

__global__ void __launch_bounds__(THREADS, 2)
fused_kernel(const float* __restrict__ scores_top,
             const float* __restrict__ scores,
             const float* __restrict__ labels,
             float* __restrict__ out)
{
    __shared__ int   hist[NBINS];
    __shared__ float red[THREADS / 32][TOPK];

    const int b    = blockIdx.x;
    const int tid  = threadIdx.x;
    const int lane = tid & 31;
    const int warp = tid >> 5;

    const float SCALE    = (float)NBINS / (RHI - RLO);
    const float INVSCALE = (RHI - RLO) / (float)NBINS;
    const float OFF      = -RLO * SCALE;
    const float BMAX     = (float)(NBINS - 1);

    // C[j] = exp(top[b][j])  (broadcast loads, tiny)
    float C[TOPK];
    const float* trow = scores_top + b * TOPK;
#pragma unroll
    for (int j = 0; j < TOPK; j++) C[j] = __expf(trow[j]);

    // Vectorized zero-init: 2048 ints = 512 int4 stores
    {
        int4 z = make_int4(0, 0, 0, 0);
        ((int4*)hist)[tid] = z;
    }
    __syncthreads();

    // ---- Pass 1: integer histogram of this row's scores (deterministic) ----
    // Manual 2x unroll: front-batch two LDG.128 per iteration for MLP.
    const float4* row4 = (const float4*)(scores + (size_t)b * NSCORES);
    const int per = NSCORES / 4;   // 12500
    for (int i = tid; i < per; i += 2 * THREADS) {
        int i2 = i + THREADS;
        bool have2 = (i2 < per);
        float4 v0 = row4[i];
        float4 v1 = have2 ? row4[i2] : make_float4(0.f, 0.f, 0.f, 0.f);

        float u0 = fminf(fmaxf(fmaf(v0.x, SCALE, OFF), 0.0f), BMAX);
        float u1 = fminf(fmaxf(fmaf(v0.y, SCALE, OFF), 0.0f), BMAX);
        float u2 = fminf(fmaxf(fmaf(v0.z, SCALE, OFF), 0.0f), BMAX);
        float u3 = fminf(fmaxf(fmaf(v0.w, SCALE, OFF), 0.0f), BMAX);
        atomicAdd(&hist[(int)u0], 1);
        atomicAdd(&hist[(int)u1], 1);
        atomicAdd(&hist[(int)u2], 1);
        atomicAdd(&hist[(int)u3], 1);

        if (have2) {
            float w0 = fminf(fmaxf(fmaf(v1.x, SCALE, OFF), 0.0f), BMAX);
            float w1 = fminf(fmaxf(fmaf(v1.y, SCALE, OFF), 0.0f), BMAX);
            float w2 = fminf(fmaxf(fmaf(v1.z, SCALE, OFF), 0.0f), BMAX);
            float w3 = fminf(fmaxf(fmaf(v1.w, SCALE, OFF), 0.0f), BMAX);
            atomicAdd(&hist[(int)w0], 1);
            atomicAdd(&hist[(int)w1], 1);
            atomicAdd(&hist[(int)w2], 1);
            atomicAdd(&hist[(int)w3], 1);
        }
    }
    __syncthreads();

    // ---- Pass 2: acc[j] -= cnt_b * sigmoid(c_b - t_j) over bins ----
    float acc[TOPK];
#pragma unroll
    for (int j = 0; j < TOPK; j++) acc[j] = 0.0f;

    for (int bin = tid; bin < NBINS; bin += THREADS) {
        int cnt = hist[bin];
        if (cnt == 0) continue;
        float cf = (float)cnt;
        float c  = fmaf((float)bin + 0.5f, INVSCALE, RLO);
        float E  = __expf(-c);                 // one MUFU per bin, shared by 20 j
#pragma unroll
        for (int j = 0; j < TOPK; j++) {
            float d = fmaf(C[j], E, 1.0f);     // 1 + e^{t_j - c_b}
            float w = fast_neg_rcp(d);         // ~ -sigmoid(c_b - t_j)
            acc[j] = fmaf(cf, w, acc[j]);
        }
    }

    // ---- Block reduction of the 20 accumulators ----
#pragma unroll
    for (int j = 0; j < TOPK; j++) {
        float v = acc[j];
#pragma unroll
        for (int off = 16; off; off >>= 1)
            v += __shfl_xor_sync(0xffffffffu, v, off);
        if (lane == 0) red[warp][j] = v;
    }
    __syncthreads();

    // ---- Fused epilogue: warp 0 only (20 active lanes) ----
    if (tid < 32) {
        const int j = lane;
        const bool valid = (j < TOPK);
        const unsigned mask = 0xffffffffu;

        float s = 0.0f;
        if (valid) {
#pragma unroll
            for (int w = 0; w < THREADS / 32; w++) s += red[w][j];
        }
        // acc held negative sums: ranks = sum(sigmoid) + 0.5 = 0.5 - s
        float rank = valid ? (0.5f - s) : 1.0f;
        float lab  = valid ? labels[b * TOPK + j] : 0.0f;

        float d  = log2f(rank + 1.0f);
        float dg = valid ? (lab / d) : 0.0f;

        // inclusive scan -> dcg
        float dcg = dg;
#pragma unroll
        for (int off = 1; off < 32; off <<= 1) {
            float y = __shfl_up_sync(mask, dcg, off);
            if (j >= off) dcg += y;
        }

        // k_sum
        float ls = lab;
#pragma unroll
        for (int off = 16; off; off >>= 1) ls += __shfl_xor_sync(mask, ls, off);
        int ksum = __float2int_rn(ls);

        // idcg inclusive scan: idcg[j] = sum_{i<=j} 1/log2(i+2)
        float ic = valid ? (1.0f / log2f((float)j + 2.0f)) : 0.0f;
        float idcg = ic;
#pragma unroll
        for (int off = 1; off < 32; off <<= 1) {
            float y = __shfl_up_sync(mask, idcg, off);
            if (j >= off) idcg += y;
        }

        int kcl = min(ksum, j + 1);
        int idx = kcl - 1;
        if (idx < 0) idx = 0;                 // only when ksum==0 -> dcg==0 anyway
        float denom = __shfl_sync(mask, idcg, idx);

        if (valid) out[b * TOPK + j] = dcg / denom;
    }
}

extern "C" void kernel_launch(void* const* d_in, const int* in_sizes, int n_in,
                              void* d_out, int out_size)
{
    // metadata order: scores_top (B*TOPK), scores (B*N), labels (B*TOPK).
    // Identify `scores` by its unique size; keep relative order of the others.
    int si = 1;
    for (int i = 0; i < n_in; i++)
        if (in_sizes[i] == BATCH * NSCORES) { si = i; break; }
    int rest[2], r = 0;
    for (int i = 0; i < n_in && r < 2; i++)
        if (i != si) rest[r++] = i;

    const float* scores_top = (const float*)d_in[rest[0]];
    const float* scores     = (const float*)d_in[si];
    const float* labels     = (const float*)d_in[rest[1]];
    float* out = (float*)d_out;

    fused_kernel<<<BATCH, THREADS>>>(scores_top, scores, labels, out);
}